// round 3
// baseline (speedup 1.0000x reference)
#include <cuda_runtime.h>
#include <math.h>

// Problem constants
#define T_ 256
#define B_ 64
#define P_ 1024
#define H_ 512

#define DECAY 0.999f

// Step-kernel tiling
#define RPB 64                 // pat rows per block
#define NWARP 8                // warps per block (256 threads)
#define RPW (RPB / NWARP)      // 8 rows per warp
#define BPB (P_ / RPB)         // 16 blocks per batch
#define NBLK (B_ * BPB)        // 1024 blocks per step

// Persistent state (static __device__ scratch — no runtime allocation)
__device__ float g_pat[(size_t)B_ * P_ * H_];   // 128 MB carried pattern state
__device__ float g_raw[2][B_ * P_];             // double-buffered pattern responses

// ---------------------------------------------------------------------------
// raw0: raw[b,p] = pat_in[b,p,:] . x[0,b,:]   (one warp per row)
// ---------------------------------------------------------------------------
__global__ __launch_bounds__(256) void raw0_kernel(const float* __restrict__ x,
                                                   const float* __restrict__ pat) {
    int gw = (blockIdx.x * 256 + threadIdx.x) >> 5;   // global warp = row id
    int lane = threadIdx.x & 31;
    int b = gw >> 10;           // /P_
    int p = gw & (P_ - 1);
    const float* row = pat + ((size_t)b * P_ + p) * H_;
    const float* xb = x + (size_t)b * H_;             // t = 0
    float d = 0.f;
#pragma unroll
    for (int j = 0; j < 4; j++) {
        int h = j * 128 + lane * 4;
        float4 o = *reinterpret_cast<const float4*>(row + h);
        float4 xv = *reinterpret_cast<const float4*>(xb + h);
        d += o.x * xv.x + o.y * xv.y + o.z * xv.z + o.w * xv.w;
    }
#pragma unroll
    for (int off = 16; off; off >>= 1) d += __shfl_xor_sync(0xffffffffu, d, off);
    if (lane == 0) g_raw[0][b * P_ + p] = d;
}

// ---------------------------------------------------------------------------
// One recurrence step, fully fused:
//   - per-block recompute of softmax stats from raw[b,:] (L2-resident, bitwise
//     identical across blocks of the same b)
//   - per row: pr, new_h accumulation (old pat), pat update + L2 normalize,
//     and raw_{t+1} = new_row . x_{t+1} computed from registers
//   - block-reduced new_h partials atomically added into out[t,b,:]
// Block order reverses on odd t so each step's pat read hits the lines the
// previous step wrote last (L2 ping-pong; pat ~ L2 capacity).
// ---------------------------------------------------------------------------
__global__ __launch_bounds__(256) void step_kernel(const float* __restrict__ x,
                                                   const float* __restrict__ pat_in,
                                                   float* __restrict__ out, int t) {
    __shared__ float s_red[256];
    __shared__ float s_acc[NWARP * H_];   // per-warp new_h partials (16 KB)

    int bid = blockIdx.x;
    if (t & 1) bid = NBLK - 1 - bid;      // alternate traversal direction
    int b = bid / BPB;
    int pblk = bid % BPB;
    int tid = threadIdx.x;
    int warp = tid >> 5, lane = tid & 31;

    const float* rawv = g_raw[t & 1] + b * P_;

    // ---- max over raw[b,:] ----
    float lm = -1e30f;
    for (int i = tid; i < P_; i += 256) lm = fmaxf(lm, rawv[i]);
    s_red[tid] = lm;
    __syncthreads();
    for (int s = 128; s > 0; s >>= 1) {
        if (tid < s) s_red[tid] = fmaxf(s_red[tid], s_red[tid + s]);
        __syncthreads();
    }
    float m = s_red[0];
    float thr = 0.9f * m;
    float sc = 10.f / m;
    __syncthreads();

    // ---- softmax denominator: sum exp(logit - 10) ----
    float ls = 0.f;
    for (int i = tid; i < P_; i += 256) {
        float r = rawv[i];
        float logit = (r >= thr) ? r * sc : 0.f;
        ls += __expf(logit - 10.f);
    }
    s_red[tid] = ls;
    __syncthreads();
    for (int s = 128; s > 0; s >>= 1) {
        if (tid < s) s_red[tid] += s_red[tid + s];
        __syncthreads();
    }
    float invden = 1.f / s_red[0];

    // ---- main per-row work ----
    const float* src = (t == 0) ? pat_in : (const float*)g_pat;
    const float* xb = x + ((size_t)t * B_ + b) * H_;
    const bool last = (t == T_ - 1);
    const float* xb1 = last ? xb : x + ((size_t)(t + 1) * B_ + b) * H_;
    float* rawn = g_raw[(t + 1) & 1] + b * P_;

    float4 xv[4], x1[4];
#pragma unroll
    for (int j = 0; j < 4; j++) {
        int h = j * 128 + lane * 4;
        xv[j] = *reinterpret_cast<const float4*>(xb + h);
        x1[j] = *reinterpret_cast<const float4*>(xb1 + h);
    }

    float acc[16];
#pragma unroll
    for (int i = 0; i < 16; i++) acc[i] = 0.f;

    int p0 = pblk * RPB + warp * RPW;
    for (int rr = 0; rr < RPW; rr++) {
        int p = p0 + rr;
        float r = rawv[p];
        float logit = (r >= thr) ? r * sc : 0.f;
        float pr = __expf(logit - 10.f) * invden;

        const float* row = src + ((size_t)b * P_ + p) * H_;
        float* wrow = g_pat + ((size_t)b * P_ + p) * H_;

        float4 nv[4];
        float ss = 0.f, d1 = 0.f;
#pragma unroll
        for (int j = 0; j < 4; j++) {
            int h = j * 128 + lane * 4;
            float4 o = *reinterpret_cast<const float4*>(row + h);
            // new_h contribution uses the OLD pat row
            acc[j * 4 + 0] += pr * o.x;
            acc[j * 4 + 1] += pr * o.y;
            acc[j * 4 + 2] += pr * o.z;
            acc[j * 4 + 3] += pr * o.w;
            float4 n;
            n.x = DECAY * o.x + pr * xv[j].x;
            n.y = DECAY * o.y + pr * xv[j].y;
            n.z = DECAY * o.z + pr * xv[j].z;
            n.w = DECAY * o.w + pr * xv[j].w;
            ss += n.x * n.x + n.y * n.y + n.z * n.z + n.w * n.w;
            d1 += n.x * x1[j].x + n.y * x1[j].y + n.z * x1[j].z + n.w * x1[j].w;
            nv[j] = n;
        }
#pragma unroll
        for (int off = 16; off; off >>= 1) {
            ss += __shfl_xor_sync(0xffffffffu, ss, off);
            d1 += __shfl_xor_sync(0xffffffffu, d1, off);
        }
        float inv = 1.f / (sqrtf(ss) + 1e-10f);
#pragma unroll
        for (int j = 0; j < 4; j++) {
            int h = j * 128 + lane * 4;
            float4 w4 = make_float4(nv[j].x * inv, nv[j].y * inv,
                                    nv[j].z * inv, nv[j].w * inv);
            *reinterpret_cast<float4*>(wrow + h) = w4;
        }
        // raw_{t+1} for the normalized row = (pre-norm dot) * inv
        if (lane == 0 && !last) rawn[p] = d1 * inv;
    }

    // ---- reduce new_h partials: regs -> per-warp smem slice -> block -> gmem
    float* sw = s_acc + warp * H_;
#pragma unroll
    for (int j = 0; j < 4; j++) {
        int h = j * 128 + lane * 4;
        *reinterpret_cast<float4*>(sw + h) =
            make_float4(acc[j * 4 + 0], acc[j * 4 + 1], acc[j * 4 + 2], acc[j * 4 + 3]);
    }
    __syncthreads();
    float* op = out + ((size_t)t * B_ + b) * H_;
    for (int h = tid; h < H_; h += 256) {
        float s = 0.f;
#pragma unroll
        for (int w = 0; w < NWARP; w++) s += s_acc[w * H_ + h];
        atomicAdd(op + h, s);
    }
}

// ---------------------------------------------------------------------------
extern "C" void kernel_launch(void* const* d_in, const int* in_sizes, int n_in,
                              void* d_out, int out_size) {
    const float* x = (const float*)d_in[0];
    const float* pat = (const float*)d_in[1];
    // metadata order is x [T,B,H] then pat [B,P,H]; pick by element count to be safe
    if (n_in >= 2 && in_sizes[0] == B_ * P_ * H_) {
        x = (const float*)d_in[1];
        pat = (const float*)d_in[0];
    }
    float* out = (float*)d_out;

    // out is accumulated via atomics — zero it first
    cudaMemsetAsync(d_out, 0, (size_t)out_size * sizeof(float), 0);

    // initial pattern responses from the (already normalized) input pat
    raw0_kernel<<<(B_ * P_) / 8, 256>>>(x, pat);

    // 256 fused recurrence steps
    for (int t = 0; t < T_; t++)
        step_kernel<<<NBLK, 256>>>(x, pat, out, t);
}